// round 1
// baseline (speedup 1.0000x reference)
#include <cuda_runtime.h>
#include <math.h>

#define BATCH 32
#define HDIM 56
#define WDIM 56
#define CDIM 256
#define NHEAD 8
#define HEADD 32
#define WS 7
#define NT 49           // tokens per window
#define SHIFT 3
#define NWIN 64         // windows per image (8x8)
#define BW (BATCH*NWIN) // 2048 total windows
#define TOK (BW*NT)     // 100352 tokens
#define QKV_N 768

// Static device scratch (allocation-free rule).
__device__ float g_q[BW*NHEAD*NT*HEADD];   // [bw][nh][t][d], q pre-scaled
__device__ float g_k[BW*NHEAD*NT*HEADD];
__device__ float g_v[BW*NHEAD*NT*HEADD];
__device__ float g_ao[TOK*CDIM];           // attention output, [bw*49+t][nh*32+d]

// ---------------------------------------------------------------------------
// QKV GEMM: C[m][j] = sum_k xw[m][k] * qkv_w[j][k] + qkv_b[j]
// xw rows gathered through cyclic shift + window partition.
// 128x128x8 tile, 256 threads, 8x8 register microtile (split 4+4 at +64).
// ---------------------------------------------------------------------------
__global__ __launch_bounds__(256) void qkv_gemm(
    const float* __restrict__ x,
    const float* __restrict__ w,
    const float* __restrict__ bias)
{
    __shared__ __align__(16) float As[8*132];
    __shared__ __align__(16) float Bs[8*132];
    __shared__ int rowoff[128];

    const int tid = threadIdx.x;
    const int m0 = blockIdx.x * 128;
    const int n0 = blockIdx.y * 128;

    if (tid < 128) {
        int m  = m0 + tid;
        int bw = m / NT; int t = m - bw*NT;
        int b  = bw >> 6; int wi = bw & 63;
        int wh = wi >> 3; int wwn = wi & 7;
        int r  = t / WS;  int c = t - r*WS;
        int hs = wh*WS + r + SHIFT; if (hs >= HDIM) hs -= HDIM;
        int ws = wwn*WS + c + SHIFT; if (ws >= WDIM) ws -= WDIM;
        rowoff[tid] = ((b*HDIM + hs)*WDIM + ws) * CDIM;
    }
    __syncthreads();

    const int tx = tid & 15, ty = tid >> 4;
    float acc[8][8];
    #pragma unroll
    for (int i = 0; i < 8; i++)
        #pragma unroll
        for (int j = 0; j < 8; j++) acc[i][j] = 0.f;

    const int lrow = tid >> 1;
    const int lk4  = (tid & 1) * 4;

    for (int kb = 0; kb < 32; kb++) {
        const int k0 = kb * 8;
        float4 av = *(const float4*)(x + rowoff[lrow] + k0 + lk4);
        float4 bv = *(const float4*)(w + (size_t)(n0 + lrow)*CDIM + k0 + lk4);
        As[(lk4+0)*132 + lrow] = av.x;
        As[(lk4+1)*132 + lrow] = av.y;
        As[(lk4+2)*132 + lrow] = av.z;
        As[(lk4+3)*132 + lrow] = av.w;
        Bs[(lk4+0)*132 + lrow] = bv.x;
        Bs[(lk4+1)*132 + lrow] = bv.y;
        Bs[(lk4+2)*132 + lrow] = bv.z;
        Bs[(lk4+3)*132 + lrow] = bv.w;
        __syncthreads();

        #pragma unroll
        for (int k = 0; k < 8; k++) {
            float a[8], b[8];
            *(float4*)&a[0] = *(const float4*)&As[k*132 + ty*4];
            *(float4*)&a[4] = *(const float4*)&As[k*132 + 64 + ty*4];
            *(float4*)&b[0] = *(const float4*)&Bs[k*132 + tx*4];
            *(float4*)&b[4] = *(const float4*)&Bs[k*132 + 64 + tx*4];
            #pragma unroll
            for (int i = 0; i < 8; i++)
                #pragma unroll
                for (int j = 0; j < 8; j++)
                    acc[i][j] = fmaf(a[i], b[j], acc[i][j]);
        }
        __syncthreads();
    }

    const float scale = 0.17677669529663687f;  // 1/sqrt(32)
    #pragma unroll
    for (int i = 0; i < 8; i++) {
        int mrow = (i < 4) ? (ty*4 + i) : (64 + ty*4 + i - 4);
        int m  = m0 + mrow;
        int bw = m / NT; int t = m - bw*NT;
        int base = bw*12544 + t*32;   // 12544 = 8*49*32
        #pragma unroll
        for (int j = 0; j < 8; j++) {
            int ncol = (j < 4) ? (tx*4 + j) : (64 + tx*4 + j - 4);
            int jg = n0 + ncol;
            float v = acc[i][j] + bias[jg];
            int which = jg >> 8;
            int rem   = jg & 255;
            int nh = rem >> 5; int d = rem & 31;
            int dst = base + nh*1568 + d;  // 1568 = 49*32
            if (which == 0)      g_q[dst] = v * scale;
            else if (which == 1) g_k[dst] = v;
            else                 g_v[dst] = v;
        }
    }
}

// ---------------------------------------------------------------------------
// Attention: one block per (window, head). S = QK^T + bias + shift-mask,
// softmax rows, O = P @ V.
// ---------------------------------------------------------------------------
__global__ __launch_bounds__(256) void attn_kernel(
    const float* __restrict__ rel_table,   // [169][8]
    const int*   __restrict__ rel_idx)     // [2401]
{
    __shared__ float sq[52*33];
    __shared__ float sk[52*33];
    __shared__ __align__(16) float sv[50*36];
    __shared__ float ss[49*50];
    __shared__ int grp[49];

    const int bw = blockIdx.x;
    const int nh = blockIdx.y;
    const int tid = threadIdx.x;

    const float* qb = g_q + bw*12544 + nh*1568;
    const float* kb = g_k + bw*12544 + nh*1568;
    const float* vb = g_v + bw*12544 + nh*1568;

    for (int i = tid; i < 1568; i += 256) {
        int t = i >> 5, d = i & 31;
        sq[t*33 + d] = qb[i];
        sk[t*33 + d] = kb[i];
        sv[t*36 + d] = vb[i];
    }
    // zero padding rows 49..51 (read by unguarded inner loops)
    if (tid < 99) {
        int t = 49 + tid / 33; int d = tid % 33;
        sq[t*33 + d] = 0.f;
        sk[t*33 + d] = 0.f;
    }
    if (tid < 49) {
        int wi = bw & 63; int wh = wi >> 3, ww = wi & 7;
        int r = tid / WS, c = tid - r*WS;
        int h = wh*WS + r, wcoord = ww*WS + c;
        int gh = (h < 49) ? 0 : ((h < 53) ? 1 : 2);
        int gw = (wcoord < 49) ? 0 : ((wcoord < 53) ? 1 : 2);
        grp[tid] = gh*3 + gw;
    }
    __syncthreads();

    // S compute: tiles of 2 rows x 4 cols -> 25 * 13 = 325 tasks
    for (int task = tid; task < 325; task += 256) {
        int ip = task / 13; int jq = task - ip*13;
        int i0 = ip*2, j0 = jq*4;
        float a00=0.f,a01=0.f,a02=0.f,a03=0.f;
        float a10=0.f,a11=0.f,a12=0.f,a13=0.f;
        #pragma unroll 8
        for (int d = 0; d < 32; d++) {
            float q0 = sq[i0*33 + d];
            float q1 = sq[(i0+1)*33 + d];
            float k0v = sk[(j0+0)*33 + d];
            float k1v = sk[(j0+1)*33 + d];
            float k2v = sk[(j0+2)*33 + d];
            float k3v = sk[(j0+3)*33 + d];
            a00 = fmaf(q0,k0v,a00); a01 = fmaf(q0,k1v,a01);
            a02 = fmaf(q0,k2v,a02); a03 = fmaf(q0,k3v,a03);
            a10 = fmaf(q1,k0v,a10); a11 = fmaf(q1,k1v,a11);
            a12 = fmaf(q1,k2v,a12); a13 = fmaf(q1,k3v,a13);
        }
        float accv[2][4] = {{a00,a01,a02,a03},{a10,a11,a12,a13}};
        #pragma unroll
        for (int ii = 0; ii < 2; ii++) {
            int i = i0 + ii;
            if (i >= 49) break;
            int gi = grp[i];
            #pragma unroll
            for (int j = 0; j < 4; j++) {
                int jj = j0 + j;
                if (jj >= 49) continue;
                int bidx = rel_idx[i*49 + jj];
                float bv = rel_table[bidx*8 + nh];
                float mk = (grp[jj] == gi) ? 0.f : -100.f;
                ss[i*50 + jj] = accv[ii][j] + bv + mk;
            }
        }
    }
    __syncthreads();

    // softmax: warp per row
    {
        int warp = tid >> 5, lane = tid & 31;
        for (int row = warp; row < 49; row += 8) {
            float v0 = ss[row*50 + lane];
            float v1 = (lane + 32 < 49) ? ss[row*50 + lane + 32] : -1e30f;
            float mx = fmaxf(v0, v1);
            #pragma unroll
            for (int o = 16; o; o >>= 1) mx = fmaxf(mx, __shfl_xor_sync(0xffffffffu, mx, o));
            float e0 = __expf(v0 - mx);
            float e1 = (lane + 32 < 49) ? __expf(v1 - mx) : 0.f;
            float sm = e0 + e1;
            #pragma unroll
            for (int o = 16; o; o >>= 1) sm += __shfl_xor_sync(0xffffffffu, sm, o);
            float inv = 1.f / sm;
            ss[row*50 + lane] = e0 * inv;
            if (lane + 32 < 49) ss[row*50 + lane + 32] = e1 * inv;
        }
    }
    __syncthreads();

    // O = P @ V : tasks 25 row-pairs x 8 d-quads = 200
    if (tid < 200) {
        int ip = tid >> 3; int dq = tid & 7;
        int i0 = ip*2, d0 = dq*4;
        float o00=0.f,o01=0.f,o02=0.f,o03=0.f;
        float o10=0.f,o11=0.f,o12=0.f,o13=0.f;
        bool has1 = (i0 + 1 < 49);
        for (int j = 0; j < 49; j++) {
            float p0 = ss[i0*50 + j];
            float p1 = has1 ? ss[(i0+1)*50 + j] : 0.f;
            float4 vv = *(const float4*)&sv[j*36 + d0];
            o00 = fmaf(p0,vv.x,o00); o01 = fmaf(p0,vv.y,o01);
            o02 = fmaf(p0,vv.z,o02); o03 = fmaf(p0,vv.w,o03);
            o10 = fmaf(p1,vv.x,o10); o11 = fmaf(p1,vv.y,o11);
            o12 = fmaf(p1,vv.z,o12); o13 = fmaf(p1,vv.w,o13);
        }
        float* outp = g_ao + (size_t)(bw*NT)*CDIM + nh*32 + d0;
        float4 r0 = make_float4(o00,o01,o02,o03);
        *(float4*)(outp + (size_t)i0*CDIM) = r0;
        if (has1) {
            float4 r1 = make_float4(o10,o11,o12,o13);
            *(float4*)(outp + (size_t)(i0+1)*CDIM) = r1;
        }
    }
}

// ---------------------------------------------------------------------------
// Proj GEMM: out[m][j] = sum_k ao[m][k] * proj_w[j][k] + proj_b[j],
// scattered through window-reverse + inverse cyclic shift into d_out.
// ---------------------------------------------------------------------------
__global__ __launch_bounds__(256) void proj_gemm(
    const float* __restrict__ w,
    const float* __restrict__ bias,
    float* __restrict__ out)
{
    __shared__ __align__(16) float As[8*132];
    __shared__ __align__(16) float Bs[8*132];
    __shared__ int rowdst[128];

    const int tid = threadIdx.x;
    const int m0 = blockIdx.x * 128;
    const int n0 = blockIdx.y * 128;

    if (tid < 128) {
        int m  = m0 + tid;
        int bw = m / NT; int t = m - bw*NT;
        int b  = bw >> 6; int wi = bw & 63;
        int wh = wi >> 3; int wwn = wi & 7;
        int r  = t / WS;  int c = t - r*WS;
        int hd = wh*WS + r + SHIFT; if (hd >= HDIM) hd -= HDIM;
        int wd = wwn*WS + c + SHIFT; if (wd >= WDIM) wd -= WDIM;
        rowdst[tid] = ((b*HDIM + hd)*WDIM + wd) * CDIM;
    }
    __syncthreads();

    const int tx = tid & 15, ty = tid >> 4;
    float acc[8][8];
    #pragma unroll
    for (int i = 0; i < 8; i++)
        #pragma unroll
        for (int j = 0; j < 8; j++) acc[i][j] = 0.f;

    const int lrow = tid >> 1;
    const int lk4  = (tid & 1) * 4;

    for (int kb = 0; kb < 32; kb++) {
        const int k0 = kb * 8;
        float4 av = *(const float4*)(g_ao + (size_t)(m0 + lrow)*CDIM + k0 + lk4);
        float4 bv = *(const float4*)(w + (size_t)(n0 + lrow)*CDIM + k0 + lk4);
        As[(lk4+0)*132 + lrow] = av.x;
        As[(lk4+1)*132 + lrow] = av.y;
        As[(lk4+2)*132 + lrow] = av.z;
        As[(lk4+3)*132 + lrow] = av.w;
        Bs[(lk4+0)*132 + lrow] = bv.x;
        Bs[(lk4+1)*132 + lrow] = bv.y;
        Bs[(lk4+2)*132 + lrow] = bv.z;
        Bs[(lk4+3)*132 + lrow] = bv.w;
        __syncthreads();

        #pragma unroll
        for (int k = 0; k < 8; k++) {
            float a[8], b[8];
            *(float4*)&a[0] = *(const float4*)&As[k*132 + ty*4];
            *(float4*)&a[4] = *(const float4*)&As[k*132 + 64 + ty*4];
            *(float4*)&b[0] = *(const float4*)&Bs[k*132 + tx*4];
            *(float4*)&b[4] = *(const float4*)&Bs[k*132 + 64 + tx*4];
            #pragma unroll
            for (int i = 0; i < 8; i++)
                #pragma unroll
                for (int j = 0; j < 8; j++)
                    acc[i][j] = fmaf(a[i], b[j], acc[i][j]);
        }
        __syncthreads();
    }

    #pragma unroll
    for (int i = 0; i < 8; i++) {
        int mrow = (i < 4) ? (ty*4 + i) : (64 + ty*4 + i - 4);
        int dstb = rowdst[mrow];
        #pragma unroll
        for (int j = 0; j < 8; j++) {
            int ncol = (j < 4) ? (tx*4 + j) : (64 + tx*4 + j - 4);
            int jg = n0 + ncol;
            out[dstb + jg] = acc[i][j] + bias[jg];
        }
    }
}

extern "C" void kernel_launch(void* const* d_in, const int* in_sizes, int n_in,
                              void* d_out, int out_size)
{
    const float* x     = (const float*)d_in[0];
    const float* qkvw  = (const float*)d_in[1];
    const float* qkvb  = (const float*)d_in[2];
    const float* projw = (const float*)d_in[3];
    const float* projb = (const float*)d_in[4];
    const float* relt  = (const float*)d_in[5];
    const int*   reli  = (const int*)d_in[6];
    float* out = (float*)d_out;

    qkv_gemm<<<dim3(TOK/128, QKV_N/128), 256>>>(x, qkvw, qkvb);
    attn_kernel<<<dim3(BW, NHEAD), 256>>>(relt, reli);
    proj_gemm<<<dim3(TOK/128, CDIM/128), 256>>>(projw, projb, out);
}

// round 2
// speedup vs baseline: 1.5803x; 1.5803x over previous
#include <cuda_runtime.h>
#include <math.h>
#include <stdint.h>

#define BATCH 32
#define HDIM 56
#define WDIM 56
#define CDIM 256
#define NHEAD 8
#define HEADD 32
#define WS 7
#define NT 49
#define SHIFT 3
#define NWIN 64
#define BW (BATCH*NWIN)
#define TOK (BW*NT)
#define QKV_N 768
#define SPAD 36

// Static device scratch (allocation-free rule).
__device__ float g_q[BW*NHEAD*NT*HEADD];
__device__ float g_k[BW*NHEAD*NT*HEADD];
__device__ float g_v[BW*NHEAD*NT*HEADD];
__device__ float g_ao[TOK*CDIM];
__device__ float g_bias[NHEAD*NT*NT];      // per-head bias matrix, pre-gathered

__device__ __forceinline__ uint32_t f2tf(float f) {
    uint32_t u;
    asm("cvt.rna.tf32.f32 %0, %1;" : "=r"(u) : "f"(f));
    return u;
}

__device__ __forceinline__ void mma_tf32(float c[4],
                                         uint32_t a0, uint32_t a1, uint32_t a2, uint32_t a3,
                                         uint32_t b0, uint32_t b1) {
    asm volatile(
        "mma.sync.aligned.m16n8k8.row.col.f32.tf32.tf32.f32 "
        "{%0,%1,%2,%3}, {%4,%5,%6,%7}, {%8,%9}, {%0,%1,%2,%3};\n"
        : "+f"(c[0]), "+f"(c[1]), "+f"(c[2]), "+f"(c[3])
        : "r"(a0), "r"(a1), "r"(a2), "r"(a3), "r"(b0), "r"(b1));
}

// ---------------------------------------------------------------------------
// bias precompute: g_bias[nh][i*49+j] = rel_table[rel_idx[i*49+j]][nh]
// ---------------------------------------------------------------------------
__global__ void bias_pre(const float* __restrict__ relt, const int* __restrict__ reli) {
    int i = blockIdx.x * 256 + threadIdx.x;
    if (i < NHEAD * NT * NT) {
        int nh = i / (NT*NT);
        int j  = i - nh * (NT*NT);
        g_bias[i] = relt[reli[j] * NHEAD + nh];
    }
}

// ---------------------------------------------------------------------------
// QKV GEMM (tf32 tensor cores): 128x128 tile, K staged 32, 8 warps.
// ---------------------------------------------------------------------------
__global__ __launch_bounds__(256) void qkv_tc(
    const float* __restrict__ x,
    const float* __restrict__ w,
    const float* __restrict__ bias)
{
    __shared__ __align__(16) float As[128*SPAD];
    __shared__ __align__(16) float Bs[128*SPAD];
    __shared__ int rowoff[128];

    const int tid = threadIdx.x;
    const int m0 = blockIdx.x * 128;
    const int n0 = blockIdx.y * 128;

    if (tid < 128) {
        int m  = m0 + tid;
        int bw = m / NT; int t = m - bw*NT;
        int b  = bw >> 6; int wi = bw & 63;
        int wh = wi >> 3; int wwn = wi & 7;
        int r  = t / WS;  int c = t - r*WS;
        int hs = wh*WS + r + SHIFT; if (hs >= HDIM) hs -= HDIM;
        int ws = wwn*WS + c + SHIFT; if (ws >= WDIM) ws -= WDIM;
        rowoff[tid] = ((b*HDIM + hs)*WDIM + ws) * CDIM;
    }
    __syncthreads();

    const int warp = tid >> 5, lane = tid & 31;
    const int wm = warp >> 2, wn = warp & 3;      // 2 x 4 warp grid
    const int g = lane >> 2, q = lane & 3;

    float acc[4][4][4];
    #pragma unroll
    for (int mi = 0; mi < 4; mi++)
        #pragma unroll
        for (int ni = 0; ni < 4; ni++)
            #pragma unroll
            for (int e = 0; e < 4; e++) acc[mi][ni][e] = 0.f;

    int lr[4], lk[4];
    #pragma unroll
    for (int i = 0; i < 4; i++) {
        int lin = tid + i*256;
        lr[i] = lin >> 3;
        lk[i] = (lin & 7) * 4;
    }

    float4 abuf[4], bbuf[4];
    #pragma unroll
    for (int i = 0; i < 4; i++) {
        abuf[i] = *(const float4*)(x + rowoff[lr[i]] + lk[i]);
        bbuf[i] = *(const float4*)(w + (size_t)(n0 + lr[i])*CDIM + lk[i]);
    }

    for (int kt = 0; kt < 8; kt++) {
        #pragma unroll
        for (int i = 0; i < 4; i++) {
            float* ap = &As[lr[i]*SPAD + lk[i]];
            ap[0] = __uint_as_float(f2tf(abuf[i].x));
            ap[1] = __uint_as_float(f2tf(abuf[i].y));
            ap[2] = __uint_as_float(f2tf(abuf[i].z));
            ap[3] = __uint_as_float(f2tf(abuf[i].w));
            float* bp = &Bs[lr[i]*SPAD + lk[i]];
            bp[0] = __uint_as_float(f2tf(bbuf[i].x));
            bp[1] = __uint_as_float(f2tf(bbuf[i].y));
            bp[2] = __uint_as_float(f2tf(bbuf[i].z));
            bp[3] = __uint_as_float(f2tf(bbuf[i].w));
        }
        __syncthreads();

        if (kt < 7) {
            int k0 = (kt+1)*32;
            #pragma unroll
            for (int i = 0; i < 4; i++) {
                abuf[i] = *(const float4*)(x + rowoff[lr[i]] + k0 + lk[i]);
                bbuf[i] = *(const float4*)(w + (size_t)(n0 + lr[i])*CDIM + k0 + lk[i]);
            }
        }

        #pragma unroll
        for (int ks = 0; ks < 4; ks++) {
            const int kc = ks*8;
            uint32_t a[4][4];
            #pragma unroll
            for (int mi = 0; mi < 4; mi++) {
                int r = wm*64 + mi*16;
                a[mi][0] = __float_as_uint(As[(r+g  )*SPAD + kc + q    ]);
                a[mi][1] = __float_as_uint(As[(r+g+8)*SPAD + kc + q    ]);
                a[mi][2] = __float_as_uint(As[(r+g  )*SPAD + kc + q + 4]);
                a[mi][3] = __float_as_uint(As[(r+g+8)*SPAD + kc + q + 4]);
            }
            uint32_t b[4][2];
            #pragma unroll
            for (int ni = 0; ni < 4; ni++) {
                int cb = wn*32 + ni*8;
                b[ni][0] = __float_as_uint(Bs[(cb+g)*SPAD + kc + q    ]);
                b[ni][1] = __float_as_uint(Bs[(cb+g)*SPAD + kc + q + 4]);
            }
            #pragma unroll
            for (int mi = 0; mi < 4; mi++)
                #pragma unroll
                for (int ni = 0; ni < 4; ni++)
                    mma_tf32(acc[mi][ni], a[mi][0], a[mi][1], a[mi][2], a[mi][3],
                             b[ni][0], b[ni][1]);
        }
        __syncthreads();
    }

    const float scale = 0.17677669529663687f;
    #pragma unroll
    for (int mi = 0; mi < 4; mi++) {
        #pragma unroll
        for (int half = 0; half < 2; half++) {
            int mrow = wm*64 + mi*16 + g + half*8;
            int m  = m0 + mrow;
            int bw = m / NT; int t = m - bw*NT;
            int base = bw*12544 + t*32;
            #pragma unroll
            for (int ni = 0; ni < 4; ni++) {
                int col = n0 + wn*32 + ni*8 + q*2;
                float v0 = acc[mi][ni][half*2+0] + bias[col];
                float v1 = acc[mi][ni][half*2+1] + bias[col+1];
                int which = col >> 8;
                int rem   = col & 255;
                int nh = rem >> 5; int d = rem & 31;
                int dst = base + nh*1568 + d;
                if (which == 0)      { g_q[dst] = v0*scale; g_q[dst+1] = v1*scale; }
                else if (which == 1) { g_k[dst] = v0;       g_k[dst+1] = v1; }
                else                 { g_v[dst] = v0;       g_v[dst+1] = v1; }
            }
        }
    }
}

// ---------------------------------------------------------------------------
// Attention: one block per (window, head).
// ---------------------------------------------------------------------------
__global__ __launch_bounds__(256) void attn_kernel()
{
    __shared__ __align__(16) float sq[50*SPAD];
    __shared__ __align__(16) float sk[52*SPAD];
    __shared__ __align__(16) float sv[49*SPAD];
    __shared__ float ss[49*50];
    __shared__ int grp[49];

    const int bw = blockIdx.x;
    const int nh = blockIdx.y;
    const int tid = threadIdx.x;

    const float* qb = g_q + bw*12544 + nh*1568;
    const float* kb = g_k + bw*12544 + nh*1568;
    const float* vb = g_v + bw*12544 + nh*1568;
    const float* bb = g_bias + nh*(NT*NT);

    for (int i = tid; i < 1568; i += 256) {
        int t = i >> 5, d = i & 31;
        sq[t*SPAD + d] = qb[i];
        sk[t*SPAD + d] = kb[i];
        sv[t*SPAD + d] = vb[i];
    }
    // zero-pad: sq row 49, sk rows 49..51 (d<32 only; d>=32 never read)
    if (tid < 32)       sq[49*SPAD + tid] = 0.f;
    else if (tid < 128) { int r = 49 + (tid-32)/32; int d = (tid-32)&31; sk[r*SPAD + d] = 0.f; }
    if (tid < 49) {
        int wi = bw & 63; int wh = wi >> 3, ww = wi & 7;
        int r = tid / WS, c = tid - r*WS;
        int h = wh*WS + r, wc = ww*WS + c;
        int gh = (h < 49) ? 0 : ((h < 53) ? 1 : 2);
        int gw = (wc < 49) ? 0 : ((wc < 53) ? 1 : 2);
        grp[tid] = gh*3 + gw;
    }
    __syncthreads();

    // S = QK^T + bias + mask   (tasks: 25 row-pairs x 13 col-quads)
    for (int task = tid; task < 325; task += 256) {
        int ip = task / 13; int jq = task - ip*13;
        int i0 = ip*2, j0 = jq*4;
        float a00=0.f,a01=0.f,a02=0.f,a03=0.f;
        float a10=0.f,a11=0.f,a12=0.f,a13=0.f;
        #pragma unroll
        for (int d4 = 0; d4 < 8; d4++) {
            float4 q0 = *(const float4*)&sq[i0*SPAD + d4*4];
            float4 q1 = *(const float4*)&sq[(i0+1)*SPAD + d4*4];
            float4 k0 = *(const float4*)&sk[(j0+0)*SPAD + d4*4];
            float4 k1 = *(const float4*)&sk[(j0+1)*SPAD + d4*4];
            float4 k2 = *(const float4*)&sk[(j0+2)*SPAD + d4*4];
            float4 k3 = *(const float4*)&sk[(j0+3)*SPAD + d4*4];
            a00 = fmaf(q0.x,k0.x,fmaf(q0.y,k0.y,fmaf(q0.z,k0.z,fmaf(q0.w,k0.w,a00))));
            a01 = fmaf(q0.x,k1.x,fmaf(q0.y,k1.y,fmaf(q0.z,k1.z,fmaf(q0.w,k1.w,a01))));
            a02 = fmaf(q0.x,k2.x,fmaf(q0.y,k2.y,fmaf(q0.z,k2.z,fmaf(q0.w,k2.w,a02))));
            a03 = fmaf(q0.x,k3.x,fmaf(q0.y,k3.y,fmaf(q0.z,k3.z,fmaf(q0.w,k3.w,a03))));
            a10 = fmaf(q1.x,k0.x,fmaf(q1.y,k0.y,fmaf(q1.z,k0.z,fmaf(q1.w,k0.w,a10))));
            a11 = fmaf(q1.x,k1.x,fmaf(q1.y,k1.y,fmaf(q1.z,k1.z,fmaf(q1.w,k1.w,a11))));
            a12 = fmaf(q1.x,k2.x,fmaf(q1.y,k2.y,fmaf(q1.z,k2.z,fmaf(q1.w,k2.w,a12))));
            a13 = fmaf(q1.x,k3.x,fmaf(q1.y,k3.y,fmaf(q1.z,k3.z,fmaf(q1.w,k3.w,a13))));
        }
        float accv[2][4] = {{a00,a01,a02,a03},{a10,a11,a12,a13}};
        #pragma unroll
        for (int ii = 0; ii < 2; ii++) {
            int i = i0 + ii;
            if (i >= 49) break;
            int gi = grp[i];
            #pragma unroll
            for (int j = 0; j < 4; j++) {
                int jj = j0 + j;
                if (jj >= 49) continue;
                float bv = bb[i*49 + jj];
                float mk = (grp[jj] == gi) ? 0.f : -100.f;
                ss[i*50 + jj] = accv[ii][j] + bv + mk;
            }
        }
    }
    __syncthreads();

    // softmax: warp per row
    {
        int warp = tid >> 5, lane = tid & 31;
        for (int row = warp; row < 49; row += 8) {
            float v0 = ss[row*50 + lane];
            float v1 = (lane + 32 < 49) ? ss[row*50 + lane + 32] : -1e30f;
            float mx = fmaxf(v0, v1);
            #pragma unroll
            for (int o = 16; o; o >>= 1) mx = fmaxf(mx, __shfl_xor_sync(0xffffffffu, mx, o));
            float e0 = __expf(v0 - mx);
            float e1 = (lane + 32 < 49) ? __expf(v1 - mx) : 0.f;
            float sm = e0 + e1;
            #pragma unroll
            for (int o = 16; o; o >>= 1) sm += __shfl_xor_sync(0xffffffffu, sm, o);
            float inv = 1.f / sm;
            ss[row*50 + lane] = e0 * inv;
            if (lane + 32 < 49) ss[row*50 + lane + 32] = e1 * inv;
        }
    }
    __syncthreads();

    // O = P @ V
    if (tid < 200) {
        int ip = tid >> 3; int dq = tid & 7;
        int i0 = ip*2, d0 = dq*4;
        float o00=0.f,o01=0.f,o02=0.f,o03=0.f;
        float o10=0.f,o11=0.f,o12=0.f,o13=0.f;
        bool has1 = (i0 + 1 < 49);
        for (int j = 0; j < 49; j++) {
            float p0 = ss[i0*50 + j];
            float p1 = has1 ? ss[(i0+1)*50 + j] : 0.f;
            float4 vv = *(const float4*)&sv[j*SPAD + d0];
            o00 = fmaf(p0,vv.x,o00); o01 = fmaf(p0,vv.y,o01);
            o02 = fmaf(p0,vv.z,o02); o03 = fmaf(p0,vv.w,o03);
            o10 = fmaf(p1,vv.x,o10); o11 = fmaf(p1,vv.y,o11);
            o12 = fmaf(p1,vv.z,o12); o13 = fmaf(p1,vv.w,o13);
        }
        float* outp = g_ao + (size_t)(bw*NT)*CDIM + nh*32 + d0;
        *(float4*)(outp + (size_t)i0*CDIM) = make_float4(o00,o01,o02,o03);
        if (has1)
            *(float4*)(outp + (size_t)(i0+1)*CDIM) = make_float4(o10,o11,o12,o13);
    }
}

// ---------------------------------------------------------------------------
// Proj GEMM (tf32 tensor cores) with fused window-reverse + un-shift scatter.
// ---------------------------------------------------------------------------
__global__ __launch_bounds__(256) void proj_tc(
    const float* __restrict__ w,
    const float* __restrict__ bias,
    float* __restrict__ out)
{
    __shared__ __align__(16) float As[128*SPAD];
    __shared__ __align__(16) float Bs[128*SPAD];
    __shared__ int rowdst[128];

    const int tid = threadIdx.x;
    const int m0 = blockIdx.x * 128;
    const int n0 = blockIdx.y * 128;

    if (tid < 128) {
        int m  = m0 + tid;
        int bw = m / NT; int t = m - bw*NT;
        int b  = bw >> 6; int wi = bw & 63;
        int wh = wi >> 3; int wwn = wi & 7;
        int r  = t / WS;  int c = t - r*WS;
        int hd = wh*WS + r + SHIFT; if (hd >= HDIM) hd -= HDIM;
        int wd = wwn*WS + c + SHIFT; if (wd >= WDIM) wd -= WDIM;
        rowdst[tid] = ((b*HDIM + hd)*WDIM + wd) * CDIM;
    }
    __syncthreads();

    const int warp = tid >> 5, lane = tid & 31;
    const int wm = warp >> 2, wn = warp & 3;
    const int g = lane >> 2, q = lane & 3;

    float acc[4][4][4];
    #pragma unroll
    for (int mi = 0; mi < 4; mi++)
        #pragma unroll
        for (int ni = 0; ni < 4; ni++)
            #pragma unroll
            for (int e = 0; e < 4; e++) acc[mi][ni][e] = 0.f;

    int lr[4], lk[4];
    #pragma unroll
    for (int i = 0; i < 4; i++) {
        int lin = tid + i*256;
        lr[i] = lin >> 3;
        lk[i] = (lin & 7) * 4;
    }

    float4 abuf[4], bbuf[4];
    #pragma unroll
    for (int i = 0; i < 4; i++) {
        abuf[i] = *(const float4*)(g_ao + (size_t)(m0 + lr[i])*CDIM + lk[i]);
        bbuf[i] = *(const float4*)(w + (size_t)(n0 + lr[i])*CDIM + lk[i]);
    }

    for (int kt = 0; kt < 8; kt++) {
        #pragma unroll
        for (int i = 0; i < 4; i++) {
            float* ap = &As[lr[i]*SPAD + lk[i]];
            ap[0] = __uint_as_float(f2tf(abuf[i].x));
            ap[1] = __uint_as_float(f2tf(abuf[i].y));
            ap[2] = __uint_as_float(f2tf(abuf[i].z));
            ap[3] = __uint_as_float(f2tf(abuf[i].w));
            float* bp = &Bs[lr[i]*SPAD + lk[i]];
            bp[0] = __uint_as_float(f2tf(bbuf[i].x));
            bp[1] = __uint_as_float(f2tf(bbuf[i].y));
            bp[2] = __uint_as_float(f2tf(bbuf[i].z));
            bp[3] = __uint_as_float(f2tf(bbuf[i].w));
        }
        __syncthreads();

        if (kt < 7) {
            int k0 = (kt+1)*32;
            #pragma unroll
            for (int i = 0; i < 4; i++) {
                abuf[i] = *(const float4*)(g_ao + (size_t)(m0 + lr[i])*CDIM + k0 + lk[i]);
                bbuf[i] = *(const float4*)(w + (size_t)(n0 + lr[i])*CDIM + k0 + lk[i]);
            }
        }

        #pragma unroll
        for (int ks = 0; ks < 4; ks++) {
            const int kc = ks*8;
            uint32_t a[4][4];
            #pragma unroll
            for (int mi = 0; mi < 4; mi++) {
                int r = wm*64 + mi*16;
                a[mi][0] = __float_as_uint(As[(r+g  )*SPAD + kc + q    ]);
                a[mi][1] = __float_as_uint(As[(r+g+8)*SPAD + kc + q    ]);
                a[mi][2] = __float_as_uint(As[(r+g  )*SPAD + kc + q + 4]);
                a[mi][3] = __float_as_uint(As[(r+g+8)*SPAD + kc + q + 4]);
            }
            uint32_t b[4][2];
            #pragma unroll
            for (int ni = 0; ni < 4; ni++) {
                int cb = wn*32 + ni*8;
                b[ni][0] = __float_as_uint(Bs[(cb+g)*SPAD + kc + q    ]);
                b[ni][1] = __float_as_uint(Bs[(cb+g)*SPAD + kc + q + 4]);
            }
            #pragma unroll
            for (int mi = 0; mi < 4; mi++)
                #pragma unroll
                for (int ni = 0; ni < 4; ni++)
                    mma_tf32(acc[mi][ni], a[mi][0], a[mi][1], a[mi][2], a[mi][3],
                             b[ni][0], b[ni][1]);
        }
        __syncthreads();
    }

    #pragma unroll
    for (int mi = 0; mi < 4; mi++) {
        #pragma unroll
        for (int half = 0; half < 2; half++) {
            int mrow = wm*64 + mi*16 + g + half*8;
            int dstb = rowdst[mrow];
            #pragma unroll
            for (int ni = 0; ni < 4; ni++) {
                int col = n0 + wn*32 + ni*8 + q*2;
                float2 v;
                v.x = acc[mi][ni][half*2+0] + bias[col];
                v.y = acc[mi][ni][half*2+1] + bias[col+1];
                *(float2*)(out + dstb + col) = v;
            }
        }
    }
}

extern "C" void kernel_launch(void* const* d_in, const int* in_sizes, int n_in,
                              void* d_out, int out_size)
{
    const float* x     = (const float*)d_in[0];
    const float* qkvw  = (const float*)d_in[1];
    const float* qkvb  = (const float*)d_in[2];
    const float* projw = (const float*)d_in[3];
    const float* projb = (const float*)d_in[4];
    const float* relt  = (const float*)d_in[5];
    const int*   reli  = (const int*)d_in[6];
    float* out = (float*)d_out;

    bias_pre<<<(NHEAD*NT*NT + 255)/256, 256>>>(relt, reli);
    qkv_tc<<<dim3(TOK/128, QKV_N/128), 256>>>(x, qkvw, qkvb);
    attn_kernel<<<dim3(BW, NHEAD), 256>>>();
    proj_tc<<<dim3(TOK/128, CDIM/128), 256>>>(projw, projb, out);
}

// round 3
// speedup vs baseline: 2.3667x; 1.4976x over previous
#include <cuda_runtime.h>
#include <math.h>
#include <stdint.h>

#define BATCH 32
#define HDIM 56
#define WDIM 56
#define CDIM 256
#define NHEAD 8
#define HEADD 32
#define WS 7
#define NT 49
#define SHIFT 3
#define NWIN 64
#define BW (BATCH*NWIN)
#define TOK (BW*NT)
#define QKV_N 768
#define SPAD 36
#define SSTR 60   // score-matrix smem stride (banks g*28+q -> conflict-free)

// Static device scratch (allocation-free rule).
__device__ float g_q[BW*NHEAD*NT*HEADD];
__device__ float g_k[BW*NHEAD*NT*HEADD];
__device__ float g_v[BW*NHEAD*NT*HEADD];
__device__ float g_ao[TOK*CDIM];
__device__ float g_bias[NHEAD*NT*NT];

__device__ __forceinline__ uint32_t f2tf(float f) {
    uint32_t u;
    asm("cvt.rna.tf32.f32 %0, %1;" : "=r"(u) : "f"(f));
    return u;
}
__device__ __forceinline__ float f2tff(float f) {
    return __uint_as_float(f2tf(f));
}

__device__ __forceinline__ void mma_tf32(float c[4],
                                         uint32_t a0, uint32_t a1, uint32_t a2, uint32_t a3,
                                         uint32_t b0, uint32_t b1) {
    asm volatile(
        "mma.sync.aligned.m16n8k8.row.col.f32.tf32.tf32.f32 "
        "{%0,%1,%2,%3}, {%4,%5,%6,%7}, {%8,%9}, {%0,%1,%2,%3};\n"
        : "+f"(c[0]), "+f"(c[1]), "+f"(c[2]), "+f"(c[3])
        : "r"(a0), "r"(a1), "r"(a2), "r"(a3), "r"(b0), "r"(b1));
}

// ---------------------------------------------------------------------------
__global__ void bias_pre(const float* __restrict__ relt, const int* __restrict__ reli) {
    int i = blockIdx.x * 256 + threadIdx.x;
    if (i < NHEAD * NT * NT) {
        int nh = i / (NT*NT);
        int j  = i - nh * (NT*NT);
        g_bias[i] = relt[reli[j] * NHEAD + nh];
    }
}

// ---------------------------------------------------------------------------
// QKV GEMM (tf32 tensor cores)
// ---------------------------------------------------------------------------
__global__ __launch_bounds__(256) void qkv_tc(
    const float* __restrict__ x,
    const float* __restrict__ w,
    const float* __restrict__ bias)
{
    __shared__ __align__(16) float As[128*SPAD];
    __shared__ __align__(16) float Bs[128*SPAD];
    __shared__ int rowoff[128];

    const int tid = threadIdx.x;
    const int m0 = blockIdx.x * 128;
    const int n0 = blockIdx.y * 128;

    if (tid < 128) {
        int m  = m0 + tid;
        int bw = m / NT; int t = m - bw*NT;
        int b  = bw >> 6; int wi = bw & 63;
        int wh = wi >> 3; int wwn = wi & 7;
        int r  = t / WS;  int c = t - r*WS;
        int hs = wh*WS + r + SHIFT; if (hs >= HDIM) hs -= HDIM;
        int ws = wwn*WS + c + SHIFT; if (ws >= WDIM) ws -= WDIM;
        rowoff[tid] = ((b*HDIM + hs)*WDIM + ws) * CDIM;
    }
    __syncthreads();

    const int warp = tid >> 5, lane = tid & 31;
    const int wm = warp >> 2, wn = warp & 3;
    const int g = lane >> 2, q = lane & 3;

    float acc[4][4][4];
    #pragma unroll
    for (int mi = 0; mi < 4; mi++)
        #pragma unroll
        for (int ni = 0; ni < 4; ni++)
            #pragma unroll
            for (int e = 0; e < 4; e++) acc[mi][ni][e] = 0.f;

    int lr[4], lk[4];
    #pragma unroll
    for (int i = 0; i < 4; i++) {
        int lin = tid + i*256;
        lr[i] = lin >> 3;
        lk[i] = (lin & 7) * 4;
    }

    float4 abuf[4], bbuf[4];
    #pragma unroll
    for (int i = 0; i < 4; i++) {
        abuf[i] = *(const float4*)(x + rowoff[lr[i]] + lk[i]);
        bbuf[i] = *(const float4*)(w + (size_t)(n0 + lr[i])*CDIM + lk[i]);
    }

    for (int kt = 0; kt < 8; kt++) {
        #pragma unroll
        for (int i = 0; i < 4; i++) {
            float* ap = &As[lr[i]*SPAD + lk[i]];
            ap[0] = f2tff(abuf[i].x); ap[1] = f2tff(abuf[i].y);
            ap[2] = f2tff(abuf[i].z); ap[3] = f2tff(abuf[i].w);
            float* bp = &Bs[lr[i]*SPAD + lk[i]];
            bp[0] = f2tff(bbuf[i].x); bp[1] = f2tff(bbuf[i].y);
            bp[2] = f2tff(bbuf[i].z); bp[3] = f2tff(bbuf[i].w);
        }
        __syncthreads();

        if (kt < 7) {
            int k0 = (kt+1)*32;
            #pragma unroll
            for (int i = 0; i < 4; i++) {
                abuf[i] = *(const float4*)(x + rowoff[lr[i]] + k0 + lk[i]);
                bbuf[i] = *(const float4*)(w + (size_t)(n0 + lr[i])*CDIM + k0 + lk[i]);
            }
        }

        #pragma unroll
        for (int ks = 0; ks < 4; ks++) {
            const int kc = ks*8;
            uint32_t a[4][4];
            #pragma unroll
            for (int mi = 0; mi < 4; mi++) {
                int r = wm*64 + mi*16;
                a[mi][0] = __float_as_uint(As[(r+g  )*SPAD + kc + q    ]);
                a[mi][1] = __float_as_uint(As[(r+g+8)*SPAD + kc + q    ]);
                a[mi][2] = __float_as_uint(As[(r+g  )*SPAD + kc + q + 4]);
                a[mi][3] = __float_as_uint(As[(r+g+8)*SPAD + kc + q + 4]);
            }
            uint32_t b[4][2];
            #pragma unroll
            for (int ni = 0; ni < 4; ni++) {
                int cb = wn*32 + ni*8;
                b[ni][0] = __float_as_uint(Bs[(cb+g)*SPAD + kc + q    ]);
                b[ni][1] = __float_as_uint(Bs[(cb+g)*SPAD + kc + q + 4]);
            }
            #pragma unroll
            for (int mi = 0; mi < 4; mi++)
                #pragma unroll
                for (int ni = 0; ni < 4; ni++)
                    mma_tf32(acc[mi][ni], a[mi][0], a[mi][1], a[mi][2], a[mi][3],
                             b[ni][0], b[ni][1]);
        }
        __syncthreads();
    }

    const float scale = 0.17677669529663687f;
    #pragma unroll
    for (int mi = 0; mi < 4; mi++) {
        #pragma unroll
        for (int half = 0; half < 2; half++) {
            int mrow = wm*64 + mi*16 + g + half*8;
            int m  = m0 + mrow;
            int bw = m / NT; int t = m - bw*NT;
            int base = bw*12544 + t*32;
            #pragma unroll
            for (int ni = 0; ni < 4; ni++) {
                int col = n0 + wn*32 + ni*8 + q*2;
                float v0 = acc[mi][ni][half*2+0] + bias[col];
                float v1 = acc[mi][ni][half*2+1] + bias[col+1];
                int which = col >> 8;
                int rem   = col & 255;
                int nh = rem >> 5; int d = rem & 31;
                int dst = base + nh*1568 + d;
                if (which == 0)      { g_q[dst] = v0*scale; g_q[dst+1] = v1*scale; }
                else if (which == 1) { g_k[dst] = v0;       g_k[dst+1] = v1; }
                else                 { g_v[dst] = v0;       g_v[dst+1] = v1; }
            }
        }
    }
}

// ---------------------------------------------------------------------------
// Attention (tf32 tensor cores): one block per (window, head), 8 warps.
// S = QK^T (28 m16n8 tiles, k=32), softmax, O = P V (16 tiles, k=56 padded).
// ---------------------------------------------------------------------------
__global__ __launch_bounds__(256) void attn_tc()
{
    __shared__ __align__(16) float sq[NT*SPAD];      // Q  [t][d]   tf32
    __shared__ __align__(16) float sk[NT*SPAD];      // K  [t][d]   tf32
    __shared__ __align__(16) float svt[HEADD*SSTR];  // V^T [d][t]  tf32, cols 49..55 zero
    __shared__ __align__(16) float ss[NT*SSTR];      // S / P, cols 49..55 zero
    __shared__ int grp[NT];

    const int bw = blockIdx.x;
    const int nh = blockIdx.y;
    const int tid = threadIdx.x;

    const float* qb = g_q + bw*12544 + nh*1568;
    const float* kb = g_k + bw*12544 + nh*1568;
    const float* vb = g_v + bw*12544 + nh*1568;
    const float* bb = g_bias + nh*(NT*NT);

    // load Q,K,V (float4) -> smem, converting to tf32; V transposed
    for (int i = tid; i < 392; i += 256) {
        int e = i*4; int t = e >> 5; int d = e & 31;
        float4 q4 = *(const float4*)(qb + e);
        float4 k4 = *(const float4*)(kb + e);
        float4 v4 = *(const float4*)(vb + e);
        float* qp = &sq[t*SPAD + d];
        qp[0]=f2tff(q4.x); qp[1]=f2tff(q4.y); qp[2]=f2tff(q4.z); qp[3]=f2tff(q4.w);
        float* kp = &sk[t*SPAD + d];
        kp[0]=f2tff(k4.x); kp[1]=f2tff(k4.y); kp[2]=f2tff(k4.z); kp[3]=f2tff(k4.w);
        svt[(d+0)*SSTR + t] = f2tff(v4.x);
        svt[(d+1)*SSTR + t] = f2tff(v4.y);
        svt[(d+2)*SSTR + t] = f2tff(v4.z);
        svt[(d+3)*SSTR + t] = f2tff(v4.w);
    }
    // zero pad columns 49..55 of svt (k-pad in PV) and ss (P pad cols)
    if (tid < 224) { int d = tid >> 3; int c = 49 + (tid & 7); if ((tid&7) < 7) svt[d*SSTR + c] = 0.f; }
    for (int i = tid; i < 343; i += 256) { int r = i / 7; int c = 49 + i % 7; ss[r*SSTR + c] = 0.f; }
    if (tid < 49) {
        int wi = bw & 63; int wh = wi >> 3, ww = wi & 7;
        int r = tid / WS, c = tid - r*WS;
        int h = wh*WS + r, wc = ww*WS + c;
        int gh = (h < 49) ? 0 : ((h < 53) ? 1 : 2);
        int gw = (wc < 49) ? 0 : ((wc < 53) ? 1 : 2);
        grp[tid] = gh*3 + gw;
    }
    __syncthreads();

    const int warp = tid >> 5, lane = tid & 31;
    const int g = lane >> 2, q = lane & 3;

    // ---- S = Q K^T + bias + mask ----
    for (int t = warp; t < 28; t += 8) {
        int mt = t / 7, nt = t - mt*7;
        int i0 = mt*16, j0 = nt*8;
        int ra = min(i0 + g, 48);
        int rb = min(i0 + g + 8, 48);
        int rn = min(j0 + g, 48);
        float c[4] = {0.f, 0.f, 0.f, 0.f};
        #pragma unroll
        for (int ks = 0; ks < 4; ks++) {
            int kc = ks*8;
            uint32_t a0 = __float_as_uint(sq[ra*SPAD + kc + q]);
            uint32_t a1 = __float_as_uint(sq[rb*SPAD + kc + q]);
            uint32_t a2 = __float_as_uint(sq[ra*SPAD + kc + q + 4]);
            uint32_t a3 = __float_as_uint(sq[rb*SPAD + kc + q + 4]);
            uint32_t b0 = __float_as_uint(sk[rn*SPAD + kc + q]);
            uint32_t b1 = __float_as_uint(sk[rn*SPAD + kc + q + 4]);
            mma_tf32(c, a0, a1, a2, a3, b0, b1);
        }
        int r0 = i0 + g, r1 = i0 + g + 8;
        int c0 = j0 + 2*q, c1 = c0 + 1;
        if (r0 < 49) {
            int gi = grp[r0];
            if (c0 < 49) ss[r0*SSTR + c0] = c[0] + bb[r0*49 + c0] + ((grp[c0]==gi)?0.f:-100.f);
            if (c1 < 49) ss[r0*SSTR + c1] = c[1] + bb[r0*49 + c1] + ((grp[c1]==gi)?0.f:-100.f);
        }
        if (r1 < 49) {
            int gi = grp[r1];
            if (c0 < 49) ss[r1*SSTR + c0] = c[2] + bb[r1*49 + c0] + ((grp[c0]==gi)?0.f:-100.f);
            if (c1 < 49) ss[r1*SSTR + c1] = c[3] + bb[r1*49 + c1] + ((grp[c1]==gi)?0.f:-100.f);
        }
    }
    __syncthreads();

    // ---- softmax (warp per row), write back tf32-rounded P ----
    for (int row = warp; row < 49; row += 8) {
        float v0 = ss[row*SSTR + lane];
        float v1 = (lane + 32 < 49) ? ss[row*SSTR + lane + 32] : -1e30f;
        float mx = fmaxf(v0, v1);
        #pragma unroll
        for (int o = 16; o; o >>= 1) mx = fmaxf(mx, __shfl_xor_sync(0xffffffffu, mx, o));
        float e0 = __expf(v0 - mx);
        float e1 = (lane + 32 < 49) ? __expf(v1 - mx) : 0.f;
        float sm = e0 + e1;
        #pragma unroll
        for (int o = 16; o; o >>= 1) sm += __shfl_xor_sync(0xffffffffu, sm, o);
        float inv = 1.f / sm;
        ss[row*SSTR + lane] = f2tff(e0 * inv);
        if (lane + 32 < 49) ss[row*SSTR + lane + 32] = f2tff(e1 * inv);
    }
    __syncthreads();

    // ---- O = P V ----
    for (int t = warp; t < 16; t += 8) {
        int mt = t >> 2, nt = t & 3;
        int i0 = mt*16, n0 = nt*8;
        int ra = min(i0 + g, 48);
        int rb = min(i0 + g + 8, 48);
        float c[4] = {0.f, 0.f, 0.f, 0.f};
        #pragma unroll
        for (int ks = 0; ks < 7; ks++) {
            int kc = ks*8;
            uint32_t a0 = __float_as_uint(ss[ra*SSTR + kc + q]);
            uint32_t a1 = __float_as_uint(ss[rb*SSTR + kc + q]);
            uint32_t a2 = __float_as_uint(ss[ra*SSTR + kc + q + 4]);
            uint32_t a3 = __float_as_uint(ss[rb*SSTR + kc + q + 4]);
            uint32_t b0 = __float_as_uint(svt[(n0+g)*SSTR + kc + q]);
            uint32_t b1 = __float_as_uint(svt[(n0+g)*SSTR + kc + q + 4]);
            mma_tf32(c, a0, a1, a2, a3, b0, b1);
        }
        int r0 = i0 + g, r1 = i0 + g + 8;
        int col = nh*32 + n0 + 2*q;
        if (r0 < 49)
            *(float2*)(g_ao + (size_t)(bw*NT + r0)*CDIM + col) = make_float2(c[0], c[1]);
        if (r1 < 49)
            *(float2*)(g_ao + (size_t)(bw*NT + r1)*CDIM + col) = make_float2(c[2], c[3]);
    }
}

// ---------------------------------------------------------------------------
// Proj GEMM (tf32 tensor cores) with fused window-reverse + un-shift scatter.
// ---------------------------------------------------------------------------
__global__ __launch_bounds__(256) void proj_tc(
    const float* __restrict__ w,
    const float* __restrict__ bias,
    float* __restrict__ out)
{
    __shared__ __align__(16) float As[128*SPAD];
    __shared__ __align__(16) float Bs[128*SPAD];
    __shared__ int rowdst[128];

    const int tid = threadIdx.x;
    const int m0 = blockIdx.x * 128;
    const int n0 = blockIdx.y * 128;

    if (tid < 128) {
        int m  = m0 + tid;
        int bw = m / NT; int t = m - bw*NT;
        int b  = bw >> 6; int wi = bw & 63;
        int wh = wi >> 3; int wwn = wi & 7;
        int r  = t / WS;  int c = t - r*WS;
        int hd = wh*WS + r + SHIFT; if (hd >= HDIM) hd -= HDIM;
        int wd = wwn*WS + c + SHIFT; if (wd >= WDIM) wd -= WDIM;
        rowdst[tid] = ((b*HDIM + hd)*WDIM + wd) * CDIM;
    }
    __syncthreads();

    const int warp = tid >> 5, lane = tid & 31;
    const int wm = warp >> 2, wn = warp & 3;
    const int g = lane >> 2, q = lane & 3;

    float acc[4][4][4];
    #pragma unroll
    for (int mi = 0; mi < 4; mi++)
        #pragma unroll
        for (int ni = 0; ni < 4; ni++)
            #pragma unroll
            for (int e = 0; e < 4; e++) acc[mi][ni][e] = 0.f;

    int lr[4], lk[4];
    #pragma unroll
    for (int i = 0; i < 4; i++) {
        int lin = tid + i*256;
        lr[i] = lin >> 3;
        lk[i] = (lin & 7) * 4;
    }

    float4 abuf[4], bbuf[4];
    #pragma unroll
    for (int i = 0; i < 4; i++) {
        abuf[i] = *(const float4*)(g_ao + (size_t)(m0 + lr[i])*CDIM + lk[i]);
        bbuf[i] = *(const float4*)(w + (size_t)(n0 + lr[i])*CDIM + lk[i]);
    }

    for (int kt = 0; kt < 8; kt++) {
        #pragma unroll
        for (int i = 0; i < 4; i++) {
            float* ap = &As[lr[i]*SPAD + lk[i]];
            ap[0] = f2tff(abuf[i].x); ap[1] = f2tff(abuf[i].y);
            ap[2] = f2tff(abuf[i].z); ap[3] = f2tff(abuf[i].w);
            float* bp = &Bs[lr[i]*SPAD + lk[i]];
            bp[0] = f2tff(bbuf[i].x); bp[1] = f2tff(bbuf[i].y);
            bp[2] = f2tff(bbuf[i].z); bp[3] = f2tff(bbuf[i].w);
        }
        __syncthreads();

        if (kt < 7) {
            int k0 = (kt+1)*32;
            #pragma unroll
            for (int i = 0; i < 4; i++) {
                abuf[i] = *(const float4*)(g_ao + (size_t)(m0 + lr[i])*CDIM + k0 + lk[i]);
                bbuf[i] = *(const float4*)(w + (size_t)(n0 + lr[i])*CDIM + k0 + lk[i]);
            }
        }

        #pragma unroll
        for (int ks = 0; ks < 4; ks++) {
            const int kc = ks*8;
            uint32_t a[4][4];
            #pragma unroll
            for (int mi = 0; mi < 4; mi++) {
                int r = wm*64 + mi*16;
                a[mi][0] = __float_as_uint(As[(r+g  )*SPAD + kc + q    ]);
                a[mi][1] = __float_as_uint(As[(r+g+8)*SPAD + kc + q    ]);
                a[mi][2] = __float_as_uint(As[(r+g  )*SPAD + kc + q + 4]);
                a[mi][3] = __float_as_uint(As[(r+g+8)*SPAD + kc + q + 4]);
            }
            uint32_t b[4][2];
            #pragma unroll
            for (int ni = 0; ni < 4; ni++) {
                int cb = wn*32 + ni*8;
                b[ni][0] = __float_as_uint(Bs[(cb+g)*SPAD + kc + q    ]);
                b[ni][1] = __float_as_uint(Bs[(cb+g)*SPAD + kc + q + 4]);
            }
            #pragma unroll
            for (int mi = 0; mi < 4; mi++)
                #pragma unroll
                for (int ni = 0; ni < 4; ni++)
                    mma_tf32(acc[mi][ni], a[mi][0], a[mi][1], a[mi][2], a[mi][3],
                             b[ni][0], b[ni][1]);
        }
        __syncthreads();
    }

    #pragma unroll
    for (int mi = 0; mi < 4; mi++) {
        #pragma unroll
        for (int half = 0; half < 2; half++) {
            int mrow = wm*64 + mi*16 + g + half*8;
            int dstb = rowdst[mrow];
            #pragma unroll
            for (int ni = 0; ni < 4; ni++) {
                int col = n0 + wn*32 + ni*8 + q*2;
                float2 v;
                v.x = acc[mi][ni][half*2+0] + bias[col];
                v.y = acc[mi][ni][half*2+1] + bias[col+1];
                *(float2*)(out + dstb + col) = v;
            }
        }
    }
}

extern "C" void kernel_launch(void* const* d_in, const int* in_sizes, int n_in,
                              void* d_out, int out_size)
{
    const float* x     = (const float*)d_in[0];
    const float* qkvw  = (const float*)d_in[1];
    const float* qkvb  = (const float*)d_in[2];
    const float* projw = (const float*)d_in[3];
    const float* projb = (const float*)d_in[4];
    const float* relt  = (const float*)d_in[5];
    const int*   reli  = (const int*)d_in[6];
    float* out = (float*)d_out;

    bias_pre<<<(NHEAD*NT*NT + 255)/256, 256>>>(relt, reli);
    qkv_tc<<<dim3(TOK/128, QKV_N/128), 256>>>(x, qkvw, qkvb);
    attn_tc<<<dim3(BW, NHEAD), 256>>>();
    proj_tc<<<dim3(TOK/128, CDIM/128), 256>>>(projw, projb, out);
}

// round 4
// speedup vs baseline: 2.6445x; 1.1174x over previous
#include <cuda_runtime.h>
#include <math.h>
#include <stdint.h>

#define BATCH 32
#define HDIM 56
#define WDIM 56
#define CDIM 256
#define NHEAD 8
#define HEADD 32
#define WS 7
#define NT 49
#define SHIFT 3
#define NWIN 64
#define BW (BATCH*NWIN)
#define TOK (BW*NT)
#define QKV_N 768
#define SPAD 36
#define SSTR 60

// Static device scratch (allocation-free rule).
__device__ float g_q[BW*NHEAD*NT*HEADD];
__device__ float g_k[BW*NHEAD*NT*HEADD];
__device__ float g_v[BW*NHEAD*NT*HEADD];
__device__ float g_ao[TOK*CDIM];
__device__ float g_bias[4*NHEAD*NT*NT];   // fused (bias + shift-mask) per class/head

__device__ __forceinline__ uint32_t f2tf(float f) {
    uint32_t u;
    asm("cvt.rna.tf32.f32 %0, %1;" : "=r"(u) : "f"(f));
    return u;
}
__device__ __forceinline__ float f2tff(float f) {
    return __uint_as_float(f2tf(f));
}

__device__ __forceinline__ void mma_tf32(float c[4],
                                         uint32_t a0, uint32_t a1, uint32_t a2, uint32_t a3,
                                         uint32_t b0, uint32_t b1) {
    asm volatile(
        "mma.sync.aligned.m16n8k8.row.col.f32.tf32.tf32.f32 "
        "{%0,%1,%2,%3}, {%4,%5,%6,%7}, {%8,%9}, {%0,%1,%2,%3};\n"
        : "+f"(c[0]), "+f"(c[1]), "+f"(c[2]), "+f"(c[3])
        : "r"(a0), "r"(a1), "r"(a2), "r"(a3), "r"(b0), "r"(b1));
}

// ---------------------------------------------------------------------------
// Fused bias + shift-mask precompute. cls bit1 = (wh==7), bit0 = (ww==7).
// ---------------------------------------------------------------------------
__global__ void bias_pre2(const float* __restrict__ relt, const int* __restrict__ reli) {
    int idx = blockIdx.x * 256 + threadIdx.x;
    if (idx >= 4*NHEAD*NT*NT) return;
    int cls = idx / (NHEAD*NT*NT);
    int rem = idx - cls*(NHEAD*NT*NT);
    int nh  = rem / (NT*NT);
    int ij  = rem - nh*(NT*NT);
    int i = ij / NT, j = ij - (ij/NT)*NT;
    float b = relt[reli[ij]*NHEAD + nh];
    int ri = i / WS, ci = i - (i/WS)*WS;
    int rj = j / WS, cj = j - (j/WS)*WS;
    int ghi = (cls & 2) ? ((ri < 4) ? 1 : 2) : 0;
    int gwi = (cls & 1) ? ((ci < 4) ? 1 : 2) : 0;
    int ghj = (cls & 2) ? ((rj < 4) ? 1 : 2) : 0;
    int gwj = (cls & 1) ? ((cj < 4) ? 1 : 2) : 0;
    float mk = (ghi == ghj && gwi == gwj) ? 0.f : -100.f;
    g_bias[idx] = b + mk;
}

// ---------------------------------------------------------------------------
// QKV GEMM (tf32 tensor cores)
// ---------------------------------------------------------------------------
__global__ __launch_bounds__(256) void qkv_tc(
    const float* __restrict__ x,
    const float* __restrict__ w,
    const float* __restrict__ bias)
{
    __shared__ __align__(16) float As[128*SPAD];
    __shared__ __align__(16) float Bs[128*SPAD];
    __shared__ int rowoff[128];

    const int tid = threadIdx.x;
    const int m0 = blockIdx.x * 128;
    const int n0 = blockIdx.y * 128;

    if (tid < 128) {
        int m  = m0 + tid;
        int bw = m / NT; int t = m - bw*NT;
        int b  = bw >> 6; int wi = bw & 63;
        int wh = wi >> 3; int wwn = wi & 7;
        int r  = t / WS;  int c = t - r*WS;
        int hs = wh*WS + r + SHIFT; if (hs >= HDIM) hs -= HDIM;
        int ws = wwn*WS + c + SHIFT; if (ws >= WDIM) ws -= WDIM;
        rowoff[tid] = ((b*HDIM + hs)*WDIM + ws) * CDIM;
    }
    __syncthreads();

    const int warp = tid >> 5, lane = tid & 31;
    const int wm = warp >> 2, wn = warp & 3;
    const int g = lane >> 2, q = lane & 3;

    float acc[4][4][4];
    #pragma unroll
    for (int mi = 0; mi < 4; mi++)
        #pragma unroll
        for (int ni = 0; ni < 4; ni++)
            #pragma unroll
            for (int e = 0; e < 4; e++) acc[mi][ni][e] = 0.f;

    int lr[4], lk[4];
    #pragma unroll
    for (int i = 0; i < 4; i++) {
        int lin = tid + i*256;
        lr[i] = lin >> 3;
        lk[i] = (lin & 7) * 4;
    }

    float4 abuf[4], bbuf[4];
    #pragma unroll
    for (int i = 0; i < 4; i++) {
        abuf[i] = *(const float4*)(x + rowoff[lr[i]] + lk[i]);
        bbuf[i] = *(const float4*)(w + (size_t)(n0 + lr[i])*CDIM + lk[i]);
    }

    for (int kt = 0; kt < 8; kt++) {
        #pragma unroll
        for (int i = 0; i < 4; i++) {
            float* ap = &As[lr[i]*SPAD + lk[i]];
            ap[0] = f2tff(abuf[i].x); ap[1] = f2tff(abuf[i].y);
            ap[2] = f2tff(abuf[i].z); ap[3] = f2tff(abuf[i].w);
            float* bp = &Bs[lr[i]*SPAD + lk[i]];
            bp[0] = f2tff(bbuf[i].x); bp[1] = f2tff(bbuf[i].y);
            bp[2] = f2tff(bbuf[i].z); bp[3] = f2tff(bbuf[i].w);
        }
        __syncthreads();

        if (kt < 7) {
            int k0 = (kt+1)*32;
            #pragma unroll
            for (int i = 0; i < 4; i++) {
                abuf[i] = *(const float4*)(x + rowoff[lr[i]] + k0 + lk[i]);
                bbuf[i] = *(const float4*)(w + (size_t)(n0 + lr[i])*CDIM + k0 + lk[i]);
            }
        }

        #pragma unroll
        for (int ks = 0; ks < 4; ks++) {
            const int kc = ks*8;
            uint32_t a[4][4];
            #pragma unroll
            for (int mi = 0; mi < 4; mi++) {
                int r = wm*64 + mi*16;
                a[mi][0] = __float_as_uint(As[(r+g  )*SPAD + kc + q    ]);
                a[mi][1] = __float_as_uint(As[(r+g+8)*SPAD + kc + q    ]);
                a[mi][2] = __float_as_uint(As[(r+g  )*SPAD + kc + q + 4]);
                a[mi][3] = __float_as_uint(As[(r+g+8)*SPAD + kc + q + 4]);
            }
            uint32_t b[4][2];
            #pragma unroll
            for (int ni = 0; ni < 4; ni++) {
                int cb = wn*32 + ni*8;
                b[ni][0] = __float_as_uint(Bs[(cb+g)*SPAD + kc + q    ]);
                b[ni][1] = __float_as_uint(Bs[(cb+g)*SPAD + kc + q + 4]);
            }
            #pragma unroll
            for (int mi = 0; mi < 4; mi++)
                #pragma unroll
                for (int ni = 0; ni < 4; ni++)
                    mma_tf32(acc[mi][ni], a[mi][0], a[mi][1], a[mi][2], a[mi][3],
                             b[ni][0], b[ni][1]);
        }
        __syncthreads();
    }

    const float scale = 0.17677669529663687f;
    #pragma unroll
    for (int mi = 0; mi < 4; mi++) {
        #pragma unroll
        for (int half = 0; half < 2; half++) {
            int mrow = wm*64 + mi*16 + g + half*8;
            int m  = m0 + mrow;
            int bw = m / NT; int t = m - bw*NT;
            int base = bw*12544 + t*32;
            #pragma unroll
            for (int ni = 0; ni < 4; ni++) {
                int col = n0 + wn*32 + ni*8 + q*2;
                float v0 = acc[mi][ni][half*2+0] + bias[col];
                float v1 = acc[mi][ni][half*2+1] + bias[col+1];
                int which = col >> 8;
                int rem   = col & 255;
                int nh = rem >> 5; int d = rem & 31;
                int dst = base + nh*1568 + d;
                if (which == 0)      { g_q[dst] = v0*scale; g_q[dst+1] = v1*scale; }
                else if (which == 1) { g_k[dst] = v0;       g_k[dst+1] = v1; }
                else                 { g_v[dst] = v0;       g_v[dst+1] = v1; }
            }
        }
    }
}

// ---------------------------------------------------------------------------
// Attention v3: 128 threads/block, one (window, head) per block.
// Warp w owns S-rows [16w, 16w+16): S = QK^T via mma (A cached in regs),
// softmax fully in registers (quad shuffles), P -> smem (aliased over Q),
// O = P V via mma.
// ---------------------------------------------------------------------------
__global__ __launch_bounds__(128) void attn_tc3()
{
    __shared__ __align__(16) float sbuf[NT*SSTR];   // P (49x60); prologue holds Q (49x36)
    __shared__ __align__(16) float sk[NT*SPAD];
    __shared__ __align__(16) float svt[HEADD*SSTR]; // V^T, cols 49..55 zeroed

    const int bw = blockIdx.x;
    const int nh = blockIdx.y;
    const int tid = threadIdx.x;

    const float* qb = g_q + bw*12544 + nh*1568;
    const float* kb = g_k + bw*12544 + nh*1568;
    const float* vb = g_v + bw*12544 + nh*1568;

    for (int i = tid; i < 392; i += 128) {
        int e = i*4; int t = e >> 5; int d = e & 31;
        float4 q4 = *(const float4*)(qb + e);
        float4 k4 = *(const float4*)(kb + e);
        float4 v4 = *(const float4*)(vb + e);
        float* qp = &sbuf[t*SPAD + d];
        qp[0]=f2tff(q4.x); qp[1]=f2tff(q4.y); qp[2]=f2tff(q4.z); qp[3]=f2tff(q4.w);
        float* kp = &sk[t*SPAD + d];
        kp[0]=f2tff(k4.x); kp[1]=f2tff(k4.y); kp[2]=f2tff(k4.z); kp[3]=f2tff(k4.w);
        svt[(d+0)*SSTR + t] = f2tff(v4.x);
        svt[(d+1)*SSTR + t] = f2tff(v4.y);
        svt[(d+2)*SSTR + t] = f2tff(v4.z);
        svt[(d+3)*SSTR + t] = f2tff(v4.w);
    }
    for (int i = tid; i < 224; i += 128)
        svt[(i/7)*SSTR + 49 + (i - (i/7)*7)] = 0.f;
    __syncthreads();

    const int warp = tid >> 5, lane = tid & 31;
    const int g = lane >> 2, q = lane & 3;

    const int wi  = bw & 63;
    const int cls = ((((wi >> 3) == 7) ? 2 : 0) | (((wi & 7) == 7) ? 1 : 0));
    const float* bb = g_bias + (cls*NHEAD + nh)*(NT*NT);

    const int i0 = warp*16;
    const int r0 = i0 + g, r1 = r0 + 8;
    const int ra = min(r0, 48), rb = min(r1, 48);
    const bool v0ok = (r0 < 49), v1ok = (r1 < 49);

    // ---- S = Q K^T (A fragments cached across all 7 n-tiles) ----
    uint32_t a[4][4];
    #pragma unroll
    for (int k4i = 0; k4i < 4; k4i++) {
        int kc = k4i*8;
        a[k4i][0] = __float_as_uint(sbuf[ra*SPAD + kc + q    ]);
        a[k4i][1] = __float_as_uint(sbuf[rb*SPAD + kc + q    ]);
        a[k4i][2] = __float_as_uint(sbuf[ra*SPAD + kc + q + 4]);
        a[k4i][3] = __float_as_uint(sbuf[rb*SPAD + kc + q + 4]);
    }
    float c[7][4];
    #pragma unroll
    for (int nt = 0; nt < 7; nt++) { c[nt][0]=0.f; c[nt][1]=0.f; c[nt][2]=0.f; c[nt][3]=0.f; }
    #pragma unroll
    for (int nt = 0; nt < 7; nt++) {
        int rn = min(nt*8 + g, 48);
        #pragma unroll
        for (int k4i = 0; k4i < 4; k4i++) {
            int kc = k4i*8;
            uint32_t b0 = __float_as_uint(sk[rn*SPAD + kc + q    ]);
            uint32_t b1 = __float_as_uint(sk[rn*SPAD + kc + q + 4]);
            mma_tf32(c[nt], a[k4i][0], a[k4i][1], a[k4i][2], a[k4i][3], b0, b1);
        }
    }

    // ---- bias(+mask) add, in-register ----
    float mx0 = -1e30f, mx1 = -1e30f;
    #pragma unroll
    for (int nt = 0; nt < 7; nt++) {
        #pragma unroll
        for (int bc = 0; bc < 2; bc++) {
            int col = nt*8 + 2*q + bc;
            bool cok = (col < 49);
            float t0 = (v0ok && cok) ? (c[nt][bc]   + __ldg(&bb[r0*NT + col])) : -1e30f;
            float t1 = (v1ok && cok) ? (c[nt][2+bc] + __ldg(&bb[r1*NT + col])) : -1e30f;
            c[nt][bc]   = t0;
            c[nt][2+bc] = t1;
            mx0 = fmaxf(mx0, t0);
            mx1 = fmaxf(mx1, t1);
        }
    }
    __syncthreads();   // all reads of sbuf(Q)/sk done; sbuf can be reused as P

    // ---- softmax in registers (rows live in lane quads) ----
    mx0 = fmaxf(mx0, __shfl_xor_sync(0xffffffffu, mx0, 1));
    mx0 = fmaxf(mx0, __shfl_xor_sync(0xffffffffu, mx0, 2));
    mx1 = fmaxf(mx1, __shfl_xor_sync(0xffffffffu, mx1, 1));
    mx1 = fmaxf(mx1, __shfl_xor_sync(0xffffffffu, mx1, 2));
    float s0 = 0.f, s1 = 0.f;
    #pragma unroll
    for (int nt = 0; nt < 7; nt++) {
        c[nt][0] = __expf(c[nt][0] - mx0); s0 += c[nt][0];
        c[nt][1] = __expf(c[nt][1] - mx0); s0 += c[nt][1];
        c[nt][2] = __expf(c[nt][2] - mx1); s1 += c[nt][2];
        c[nt][3] = __expf(c[nt][3] - mx1); s1 += c[nt][3];
    }
    s0 += __shfl_xor_sync(0xffffffffu, s0, 1);
    s0 += __shfl_xor_sync(0xffffffffu, s0, 2);
    s1 += __shfl_xor_sync(0xffffffffu, s1, 1);
    s1 += __shfl_xor_sync(0xffffffffu, s1, 2);
    float inv0 = 1.f / s0, inv1 = 1.f / s1;
    #pragma unroll
    for (int nt = 0; nt < 7; nt++) {
        #pragma unroll
        for (int bc = 0; bc < 2; bc++) {
            int col = nt*8 + 2*q + bc;
            if (v0ok) sbuf[r0*SSTR + col] = (col < 49) ? f2tff(c[nt][bc]  *inv0) : 0.f;
            if (v1ok) sbuf[r1*SSTR + col] = (col < 49) ? f2tff(c[nt][2+bc]*inv1) : 0.f;
        }
    }
    __syncthreads();

    // ---- O = P V (warp keeps its rows; P fragments hoisted across d-tiles) ----
    uint32_t pa[7][4];
    #pragma unroll
    for (int k7 = 0; k7 < 7; k7++) {
        int kc = k7*8;
        pa[k7][0] = __float_as_uint(sbuf[ra*SSTR + kc + q    ]);
        pa[k7][1] = __float_as_uint(sbuf[rb*SSTR + kc + q    ]);
        pa[k7][2] = __float_as_uint(sbuf[ra*SSTR + kc + q + 4]);
        pa[k7][3] = __float_as_uint(sbuf[rb*SSTR + kc + q + 4]);
    }
    #pragma unroll
    for (int nt = 0; nt < 4; nt++) {
        int n0 = nt*8;
        float cc[4] = {0.f, 0.f, 0.f, 0.f};
        #pragma unroll
        for (int k7 = 0; k7 < 7; k7++) {
            int kc = k7*8;
            uint32_t b0 = __float_as_uint(svt[(n0+g)*SSTR + kc + q    ]);
            uint32_t b1 = __float_as_uint(svt[(n0+g)*SSTR + kc + q + 4]);
            mma_tf32(cc, pa[k7][0], pa[k7][1], pa[k7][2], pa[k7][3], b0, b1);
        }
        int col = nh*32 + n0 + 2*q;
        if (v0ok)
            *(float2*)(g_ao + (size_t)(bw*NT + r0)*CDIM + col) = make_float2(cc[0], cc[1]);
        if (v1ok)
            *(float2*)(g_ao + (size_t)(bw*NT + r1)*CDIM + col) = make_float2(cc[2], cc[3]);
    }
}

// ---------------------------------------------------------------------------
// Proj GEMM (tf32 tensor cores) with fused window-reverse + un-shift scatter.
// ---------------------------------------------------------------------------
__global__ __launch_bounds__(256) void proj_tc(
    const float* __restrict__ w,
    const float* __restrict__ bias,
    float* __restrict__ out)
{
    __shared__ __align__(16) float As[128*SPAD];
    __shared__ __align__(16) float Bs[128*SPAD];
    __shared__ int rowdst[128];

    const int tid = threadIdx.x;
    const int m0 = blockIdx.x * 128;
    const int n0 = blockIdx.y * 128;

    if (tid < 128) {
        int m  = m0 + tid;
        int bw = m / NT; int t = m - bw*NT;
        int b  = bw >> 6; int wi = bw & 63;
        int wh = wi >> 3; int wwn = wi & 7;
        int r  = t / WS;  int c = t - r*WS;
        int hd = wh*WS + r + SHIFT; if (hd >= HDIM) hd -= HDIM;
        int wd = wwn*WS + c + SHIFT; if (wd >= WDIM) wd -= WDIM;
        rowdst[tid] = ((b*HDIM + hd)*WDIM + wd) * CDIM;
    }
    __syncthreads();

    const int warp = tid >> 5, lane = tid & 31;
    const int wm = warp >> 2, wn = warp & 3;
    const int g = lane >> 2, q = lane & 3;

    float acc[4][4][4];
    #pragma unroll
    for (int mi = 0; mi < 4; mi++)
        #pragma unroll
        for (int ni = 0; ni < 4; ni++)
            #pragma unroll
            for (int e = 0; e < 4; e++) acc[mi][ni][e] = 0.f;

    int lr[4], lk[4];
    #pragma unroll
    for (int i = 0; i < 4; i++) {
        int lin = tid + i*256;
        lr[i] = lin >> 3;
        lk[i] = (lin & 7) * 4;
    }

    float4 abuf[4], bbuf[4];
    #pragma unroll
    for (int i = 0; i < 4; i++) {
        abuf[i] = *(const float4*)(g_ao + (size_t)(m0 + lr[i])*CDIM + lk[i]);
        bbuf[i] = *(const float4*)(w + (size_t)(n0 + lr[i])*CDIM + lk[i]);
    }

    for (int kt = 0; kt < 8; kt++) {
        #pragma unroll
        for (int i = 0; i < 4; i++) {
            float* ap = &As[lr[i]*SPAD + lk[i]];
            ap[0] = f2tff(abuf[i].x); ap[1] = f2tff(abuf[i].y);
            ap[2] = f2tff(abuf[i].z); ap[3] = f2tff(abuf[i].w);
            float* bp = &Bs[lr[i]*SPAD + lk[i]];
            bp[0] = f2tff(bbuf[i].x); bp[1] = f2tff(bbuf[i].y);
            bp[2] = f2tff(bbuf[i].z); bp[3] = f2tff(bbuf[i].w);
        }
        __syncthreads();

        if (kt < 7) {
            int k0 = (kt+1)*32;
            #pragma unroll
            for (int i = 0; i < 4; i++) {
                abuf[i] = *(const float4*)(g_ao + (size_t)(m0 + lr[i])*CDIM + k0 + lk[i]);
                bbuf[i] = *(const float4*)(w + (size_t)(n0 + lr[i])*CDIM + k0 + lk[i]);
            }
        }

        #pragma unroll
        for (int ks = 0; ks < 4; ks++) {
            const int kc = ks*8;
            uint32_t a[4][4];
            #pragma unroll
            for (int mi = 0; mi < 4; mi++) {
                int r = wm*64 + mi*16;
                a[mi][0] = __float_as_uint(As[(r+g  )*SPAD + kc + q    ]);
                a[mi][1] = __float_as_uint(As[(r+g+8)*SPAD + kc + q    ]);
                a[mi][2] = __float_as_uint(As[(r+g  )*SPAD + kc + q + 4]);
                a[mi][3] = __float_as_uint(As[(r+g+8)*SPAD + kc + q + 4]);
            }
            uint32_t b[4][2];
            #pragma unroll
            for (int ni = 0; ni < 4; ni++) {
                int cb = wn*32 + ni*8;
                b[ni][0] = __float_as_uint(Bs[(cb+g)*SPAD + kc + q    ]);
                b[ni][1] = __float_as_uint(Bs[(cb+g)*SPAD + kc + q + 4]);
            }
            #pragma unroll
            for (int mi = 0; mi < 4; mi++)
                #pragma unroll
                for (int ni = 0; ni < 4; ni++)
                    mma_tf32(acc[mi][ni], a[mi][0], a[mi][1], a[mi][2], a[mi][3],
                             b[ni][0], b[ni][1]);
        }
        __syncthreads();
    }

    #pragma unroll
    for (int mi = 0; mi < 4; mi++) {
        #pragma unroll
        for (int half = 0; half < 2; half++) {
            int mrow = wm*64 + mi*16 + g + half*8;
            int dstb = rowdst[mrow];
            #pragma unroll
            for (int ni = 0; ni < 4; ni++) {
                int col = n0 + wn*32 + ni*8 + q*2;
                float2 v;
                v.x = acc[mi][ni][half*2+0] + bias[col];
                v.y = acc[mi][ni][half*2+1] + bias[col+1];
                *(float2*)(out + dstb + col) = v;
            }
        }
    }
}

extern "C" void kernel_launch(void* const* d_in, const int* in_sizes, int n_in,
                              void* d_out, int out_size)
{
    const float* x     = (const float*)d_in[0];
    const float* qkvw  = (const float*)d_in[1];
    const float* qkvb  = (const float*)d_in[2];
    const float* projw = (const float*)d_in[3];
    const float* projb = (const float*)d_in[4];
    const float* relt  = (const float*)d_in[5];
    const int*   reli  = (const int*)d_in[6];
    float* out = (float*)d_out;

    bias_pre2<<<(4*NHEAD*NT*NT + 255)/256, 256>>>(relt, reli);
    qkv_tc<<<dim3(TOK/128, QKV_N/128), 256>>>(x, qkvw, qkvb);
    attn_tc3<<<dim3(BW, NHEAD), 128>>>();
    proj_tc<<<dim3(TOK/128, CDIM/128), 256>>>(projw, projb, out);
}